// round 2
// baseline (speedup 1.0000x reference)
#include <cuda_runtime.h>

#define D 128
#define H 16
#define B 8192
#define NTOT (D * H)   // 2048 = GEMM N dimension

#define MT 64          // CTA batch tile
#define NT 128         // CTA n tile (8 output variables x 16 hidden)
#define XS_PAD 68      // padded row length for transposed X tile (16B-aligned, conflict-free)

// Scratch: effective first-layer weights Weff[v][i*H + h] = A[v,i] * W1[i,v,h]
__device__ float g_Weff[D * NTOT];

// ---------------------------------------------------------------------------
// Setup: compute soft adjacency A (binary gumbel-softmax -> sigmoid form),
// write A into the output buffer tail, and build Weff.
// grid: 1024 blocks x 256 threads = 262144 threads = D*NTOT
// ---------------------------------------------------------------------------
__global__ void setup_kernel(const float* __restrict__ logits,
                             const float* __restrict__ temperature,
                             const float* __restrict__ gumbel,
                             const float* __restrict__ W1,
                             float* __restrict__ outA) {
    int idx = blockIdx.x * blockDim.x + threadIdx.x;   // [v][i][h] flattened as v*2048 + i*16 + h
    int v = idx >> 11;
    int n = idx & 2047;
    int i = n >> 4;
    int h = n & 15;

    float T  = temperature[0];
    float l  = logits[v * D + i];
    float g0 = gumbel[(v * D + i) * 2 + 0];
    float g1 = gumbel[(v * D + i) * 2 + 1];
    // softmax over {(-l+g0)/T, (l+g1)/T}, take P(on) = sigmoid(b - a)
    float a = (-l + g0) / T;
    float b = ( l + g1) / T;
    float A = 1.0f / (1.0f + expf(a - b));
    if (v == i) A = 0.0f;

    g_Weff[idx] = A * W1[i * (D * H) + v * H + h];
    if (h == 0) outA[v * D + i] = A;
}

// ---------------------------------------------------------------------------
// Fused GEMM + MLP epilogue.
// hidden[b, n] = sum_v X[b,v] * Weff[v,n]   (M=8192, N=2048, K=128)
// recon[b, i]  = sum_{h in 16-group} relu(hidden + b1) * W2  + b2
// CTA: 64 x 128 tile, 256 threads, 4x8 register micro-tiles.
// ---------------------------------------------------------------------------
__global__ void __launch_bounds__(256, 2)
dag_main_kernel(const float* __restrict__ X,
                const float* __restrict__ b1,
                const float* __restrict__ W2,
                const float* __restrict__ b2,
                float* __restrict__ out) {
    extern __shared__ float smem[];
    float* Xs = smem;                 // [K=128][MT padded to 68]  (transposed X tile)
    float* Ws = smem + D * XS_PAD;    // [K=128][NT=128]

    const int tid   = threadIdx.x;
    const int nblk  = blockIdx.x;     // 0..15
    const int mblk  = blockIdx.y;     // 0..127
    const int mbase = mblk * MT;
    const int nbase = nblk * NT;

    // ---- load X tile (coalesced float4 reads, transposed scalar smem stores)
    #pragma unroll
    for (int it = 0; it < (MT * D / 4) / 256; it++) {
        int idx = tid + it * 256;           // over 2048 float4s
        int bm  = idx >> 5;                 // row in tile (32 float4 per row)
        int v4  = idx & 31;
        float4 x = reinterpret_cast<const float4*>(X)[(size_t)(mbase + bm) * (D / 4) + v4];
        int v = v4 * 4;
        Xs[(v + 0) * XS_PAD + bm] = x.x;
        Xs[(v + 1) * XS_PAD + bm] = x.y;
        Xs[(v + 2) * XS_PAD + bm] = x.z;
        Xs[(v + 3) * XS_PAD + bm] = x.w;
    }
    // ---- load Weff tile (coalesced float4, same layout in smem)
    #pragma unroll
    for (int it = 0; it < (D * NT / 4) / 256; it++) {
        int idx = tid + it * 256;           // over 4096 float4s
        int k = idx >> 5;                   // 32 float4 per row of NT
        int j = idx & 31;
        reinterpret_cast<float4*>(Ws)[k * (NT / 4) + j] =
            reinterpret_cast<const float4*>(g_Weff)[(size_t)k * (NTOT / 4) + (nbase / 4) + j];
    }
    __syncthreads();

    const int tx = tid & 15;     // n-group
    const int ty = tid >> 4;     // m-group
    const int m0 = ty * 4;
    const int n0 = tx * 8;

    float acc[4][8];
    #pragma unroll
    for (int mm = 0; mm < 4; mm++)
        #pragma unroll
        for (int jj = 0; jj < 8; jj++) acc[mm][jj] = 0.0f;

    #pragma unroll 4
    for (int k = 0; k < D; k++) {
        float4 a4 = *reinterpret_cast<const float4*>(&Xs[k * XS_PAD + m0]);
        float4 w0 = *reinterpret_cast<const float4*>(&Ws[k * NT + n0]);
        float4 w1 = *reinterpret_cast<const float4*>(&Ws[k * NT + n0 + 4]);
        float av[4] = {a4.x, a4.y, a4.z, a4.w};
        float wv[8] = {w0.x, w0.y, w0.z, w0.w, w1.x, w1.y, w1.z, w1.w};
        #pragma unroll
        for (int mm = 0; mm < 4; mm++)
            #pragma unroll
            for (int jj = 0; jj < 8; jj++)
                acc[mm][jj] = fmaf(av[mm], wv[jj], acc[mm][jj]);
    }

    // ---- fused epilogue: relu + second layer reduction over 16 h's per i.
    // Each thread holds one 8-h half of variable i = nbase/H + tx/2.
    const int i     = (nbase / H) + (tx >> 1);
    const int hbase = (tx & 1) * 8;

    float b1v[8], w2v[8];
    #pragma unroll
    for (int j = 0; j < 8; j++) {
        b1v[j] = b1[i * H + hbase + j];
        w2v[j] = W2[i * H + hbase + j];
    }
    const float bias2 = b2[i];

    #pragma unroll
    for (int mm = 0; mm < 4; mm++) {
        float r = 0.0f;
        #pragma unroll
        for (int j = 0; j < 8; j++) {
            float hdn = fmaxf(acc[mm][j] + b1v[j], 0.0f);
            r = fmaf(hdn, w2v[j], r);
        }
        // lanes (tx even, tx odd) are adjacent -> combine the two h-halves
        float r_other = __shfl_xor_sync(0xffffffffu, r, 1);
        if ((tx & 1) == 0) {
            out[(size_t)(mbase + m0 + mm) * D + i] = r + r_other + bias2;
        }
    }
}

// ---------------------------------------------------------------------------
extern "C" void kernel_launch(void* const* d_in, const int* in_sizes, int n_in,
                              void* d_out, int out_size) {
    const float* X      = (const float*)d_in[0];  // [B, D]
    const float* logits = (const float*)d_in[1];  // [D, D]
    const float* temp   = (const float*)d_in[2];  // [1]
    const float* gumbel = (const float*)d_in[3];  // [D, D, 2]
    const float* W1     = (const float*)d_in[4];  // [D, D, H]
    const float* b1     = (const float*)d_in[5];  // [D, H]
    const float* W2     = (const float*)d_in[6];  // [D, H]
    const float* b2     = (const float*)d_in[7];  // [D]
    float* out = (float*)d_out;                   // recon [B,D] then A [D,D]

    (void)in_sizes; (void)n_in; (void)out_size;

    setup_kernel<<<(D * NTOT) / 256, 256>>>(logits, temp, gumbel, W1, out + (size_t)B * D);

    size_t smem = (size_t)(D * XS_PAD + D * NT) * sizeof(float);  // ~98 KB
    cudaFuncSetAttribute(dag_main_kernel,
                         cudaFuncAttributeMaxDynamicSharedMemorySize, (int)smem);
    dag_main_kernel<<<dim3(NTOT / NT, B / MT), 256, smem>>>(X, b1, W2, b2, out);
}

// round 11
// speedup vs baseline: 3.5548x; 3.5548x over previous
#include <cuda_runtime.h>
#include <cstdint>

#define D 128
#define H 16
#define B 8192
#define NTOT 2048              // GEMM N = D*H

#define AS_STRIDE 132          // padded K stride in words: bank = (4*r + c) % 32, conflict-free

// g_WeffT[n][k] = rna_tf32( A[k, n/H] * W1[n/H, k, n%H] )
__device__ float g_WeffT[NTOT * D];

__device__ __forceinline__ float f2tf32(float x) {
    float y; asm("cvt.rna.tf32.f32 %0, %1;" : "=f"(y) : "f"(x)); return y;
}

__device__ __forceinline__ void mma1688(float* c, const uint32_t* a, const uint32_t* b) {
    asm volatile("mma.sync.aligned.m16n8k8.row.col.f32.tf32.tf32.f32 "
        "{%0,%1,%2,%3}, {%4,%5,%6,%7}, {%8,%9}, {%0,%1,%2,%3};"
        : "+f"(c[0]), "+f"(c[1]), "+f"(c[2]), "+f"(c[3])
        : "r"(a[0]), "r"(a[1]), "r"(a[2]), "r"(a[3]), "r"(b[0]), "r"(b[1]));
}

// ---------------------------------------------------------------------------
// Setup: A (gumbel-softmax sigmoid) -> out tail; WeffT[n][v] = rna(A[v,i]*W1[i,v,h])
// ---------------------------------------------------------------------------
__global__ void setup_kernel(const float* __restrict__ logits,
                             const float* __restrict__ temperature,
                             const float* __restrict__ gumbel,
                             const float* __restrict__ W1,
                             float* __restrict__ outA) {
    int idx = blockIdx.x * blockDim.x + threadIdx.x;   // n*128 + v
    int v = idx & 127;
    int n = idx >> 7;
    int i = n >> 4;
    int h = n & 15;

    float T  = temperature[0];
    float l  = logits[v * D + i];
    float g0 = gumbel[(v * D + i) * 2 + 0];
    float g1 = gumbel[(v * D + i) * 2 + 1];
    float A = 1.0f / (1.0f + expf((g0 - g1 - 2.0f * l) / T));
    if (v == i) A = 0.0f;

    g_WeffT[idx] = f2tf32(A * W1[i * (D * H) + v * H + h]);
    if (h == 0) outA[v * D + i] = A;
}

// ---------------------------------------------------------------------------
// Tile loader: gmem row-major [128][128] f32 -> smem [row][k] with stride 132.
// float4 loads + float4 stores (132 % 4 == 0 keeps 16B alignment).
// ---------------------------------------------------------------------------
__device__ __forceinline__ void load_tile(const float* __restrict__ src,
                                          float* __restrict__ dst,
                                          int tid, bool cvt) {
    #pragma unroll 4
    for (int it = 0; it < 16; it++) {
        int idx = it * 256 + tid;          // 4096 float4s
        int r = idx >> 5;                  // row 0..127
        int c = idx & 31;                  // float4 col 0..31
        float4 v = reinterpret_cast<const float4*>(src)[idx];
        if (cvt) {
            v.x = f2tf32(v.x); v.y = f2tf32(v.y);
            v.z = f2tf32(v.z); v.w = f2tf32(v.w);
        }
        *reinterpret_cast<float4*>(&dst[r * AS_STRIDE + c * 4]) = v;
    }
}

// ---------------------------------------------------------------------------
// Main: per-CTA 128(M) x 128(N) x 128(K) tf32 mma.sync GEMM + fused MLP epilogue.
// 8 warps = 2(M) x 4(N); each warp 64x32 via 4x4 m16n8k8 tiles.
// ---------------------------------------------------------------------------
__global__ void __launch_bounds__(256, 1)
dag_mma_kernel(const float* __restrict__ X,
               const float* __restrict__ b1,
               const float* __restrict__ W2,
               const float* __restrict__ b2,
               float* __restrict__ out) {
    extern __shared__ float smem[];
    float* As = smem;                          // [128][AS_STRIDE]  X tile (m-major)
    float* Bs = smem + 128 * AS_STRIDE;        // [128][AS_STRIDE]  WeffT tile (n-major)

    const int tid   = threadIdx.x;
    const int lane  = tid & 31;
    const int wid   = tid >> 5;
    const int warp_m = wid & 1;                // 0..1 (64 rows each)
    const int warp_n = wid >> 1;               // 0..3 (32 n-cols each)
    const int r  = lane >> 2;                  // 0..7
    const int cq = lane & 3;                   // 0..3

    const int nblk  = blockIdx.x;              // 0..15
    const int mblk  = blockIdx.y;              // 0..63
    const int mbase = mblk * 128;
    const int nbase = nblk * 128;
    const int ivar0 = nblk * 8;

    load_tile(X + (size_t)mbase * D, As, tid, true);
    load_tile(g_WeffT + (size_t)nbase * D, Bs, tid, false);
    __syncthreads();

    float acc[4][4][4];
    #pragma unroll
    for (int mt = 0; mt < 4; mt++)
        #pragma unroll
        for (int nt = 0; nt < 4; nt++)
            #pragma unroll
            for (int e = 0; e < 4; e++) acc[mt][nt][e] = 0.0f;

    #pragma unroll 2
    for (int ks = 0; ks < 16; ks++) {
        const int k0 = ks * 8;
        uint32_t a[4][4], bf[4][2];
        #pragma unroll
        for (int mt = 0; mt < 4; mt++) {
            const float* ap = &As[(warp_m * 64 + mt * 16 + r) * AS_STRIDE + k0 + cq];
            a[mt][0] = __float_as_uint(ap[0]);
            a[mt][1] = __float_as_uint(ap[8 * AS_STRIDE]);
            a[mt][2] = __float_as_uint(ap[4]);
            a[mt][3] = __float_as_uint(ap[8 * AS_STRIDE + 4]);
        }
        #pragma unroll
        for (int nt = 0; nt < 4; nt++) {
            const float* bp = &Bs[(warp_n * 32 + nt * 8 + r) * AS_STRIDE + k0 + cq];
            bf[nt][0] = __float_as_uint(bp[0]);
            bf[nt][1] = __float_as_uint(bp[4]);
        }
        #pragma unroll
        for (int mt = 0; mt < 4; mt++)
            #pragma unroll
            for (int nt = 0; nt < 4; nt++)
                mma1688(acc[mt][nt], a[mt], bf[nt]);
    }

    // ---- fused epilogue: relu(+b1) . W2 + b2, reduced across the 4-lane k-groups
    // C frag: c0=(row r, col 2cq), c1=(r, 2cq+1), c2=(r+8, 2cq), c3=(r+8, 2cq+1)
    #pragma unroll
    for (int j = 0; j < 2; j++) {                      // 2 variables per warp
        const int i = ivar0 + warp_n * 2 + j;
        float b1v[4], w2v[4];
        #pragma unroll
        for (int nt2 = 0; nt2 < 2; nt2++)
            #pragma unroll
            for (int e = 0; e < 2; e++) {
                int h = nt2 * 8 + 2 * cq + e;
                b1v[nt2 * 2 + e] = __ldg(&b1[i * H + h]);
                w2v[nt2 * 2 + e] = __ldg(&W2[i * H + h]);
            }
        const float bias = __ldg(&b2[i]);
        #pragma unroll
        for (int mt = 0; mt < 4; mt++) {
            #pragma unroll
            for (int half = 0; half < 2; half++) {     // row r (+0) or r+8
                float p = 0.0f;
                #pragma unroll
                for (int nt2 = 0; nt2 < 2; nt2++) {
                    const int nt = 2 * j + nt2;
                    p = fmaf(fmaxf(acc[mt][nt][half * 2 + 0] + b1v[nt2 * 2 + 0], 0.0f),
                             w2v[nt2 * 2 + 0], p);
                    p = fmaf(fmaxf(acc[mt][nt][half * 2 + 1] + b1v[nt2 * 2 + 1], 0.0f),
                             w2v[nt2 * 2 + 1], p);
                }
                p += __shfl_xor_sync(0xffffffffu, p, 1);
                p += __shfl_xor_sync(0xffffffffu, p, 2);
                if (cq == 0) {
                    int row = mbase + warp_m * 64 + mt * 16 + half * 8 + r;
                    out[(size_t)row * D + i] = p + bias;
                }
            }
        }
    }
}

// ---------------------------------------------------------------------------
extern "C" void kernel_launch(void* const* d_in, const int* in_sizes, int n_in,
                              void* d_out, int out_size) {
    const float* X      = (const float*)d_in[0];
    const float* logits = (const float*)d_in[1];
    const float* temp   = (const float*)d_in[2];
    const float* gumbel = (const float*)d_in[3];
    const float* W1     = (const float*)d_in[4];
    const float* b1     = (const float*)d_in[5];
    const float* W2     = (const float*)d_in[6];
    const float* b2     = (const float*)d_in[7];
    float* out = (float*)d_out;
    (void)in_sizes; (void)n_in; (void)out_size;

    setup_kernel<<<(NTOT * D) / 256, 256>>>(logits, temp, gumbel, W1, out + (size_t)B * D);

    size_t smem = (size_t)(2 * 128 * AS_STRIDE) * sizeof(float);   // 135168 B
    cudaFuncSetAttribute(dag_mma_kernel,
                         cudaFuncAttributeMaxDynamicSharedMemorySize, (int)smem);
    dag_mma_kernel<<<dim3(16, 64), 256, smem>>>(X, b1, W2, b2, out);
}